// round 7
// baseline (speedup 1.0000x reference)
#include <cuda_runtime.h>

#define SDIM 8192
#define NT   1024
#define NCH  4            // chunks of 2048 elements; thread owns pair e = 2*tid

__device__ __forceinline__ float softplus_fast(float x) {
    // jax.nn.softplus = max(x,0) + log1p(exp(-|x|)); fast-math variant
    return fmaxf(x, 0.0f) + __logf(1.0f + __expf(-fabsf(x)));
}

__global__ void __launch_bounds__(NT, 2)
soc_kernel(const float4* __restrict__ X, const float* __restrict__ SC,
           const float* __restrict__ W1, const float* __restrict__ b1,
           const float* __restrict__ W2, const float* __restrict__ b2,
           const float* __restrict__ Wa, const float* __restrict__ ba,
           const float* __restrict__ Wb, const float* __restrict__ bb,
           float* __restrict__ out)
{
    // swtot[k][w]   (in-loop): warp w's chunk-k total
    // swtot[k][w]   (post-warp0): SOC_init + chunk-base_k + warp-exclusive-prefix(w)
    __shared__ float swtot[NCH][33];
    __shared__ float s_init;

    const int b    = blockIdx.x;
    const int tid  = threadIdx.x;
    const int lane = tid & 31, warp = tid >> 5;
    const float4* Xb   = X + (size_t)b * SDIM;
    float*        outb = out + (size_t)b * SDIM;

    // per-batch scalars
    const float Q    = SC[b * 4 + 0];
    const float eta0 = SC[b * 4 + 1];
    const float wa0 = Wa[0], wa1 = Wa[1], vba = ba[0];
    const float vwb = Wb[0], vbb = bb[0];
    const float scale = eta0 / (3600.0f * Q);
    // delta = scale*(1 + bb + wb*softplus(.))*I  (dt == 1.0 exactly: times = arange)
    const float Acoef = scale * (1.0f + vbb);
    const float Bcoef = scale * vwb;

    if (tid == 0) {
        const float R = SC[b * 4 + 2], sc3 = SC[b * 4 + 3];
        float4 x0 = Xb[0];
        float h = softplus_fast(x0.y * W1[0] + x0.z * W1[1] + x0.w * W1[2]
                                + R * W1[3] + b1[0]);
        s_init = sc3 * (1.0f + (h * W2[0] + b2[0]));
    }

    // thread's pair: elements 2*tid, 2*tid+1 (32 B contiguous -> perfect LDG.128)
    const float4* pe = Xb + 2 * tid;

    // depth-2 rolling prefetch
    float4 f0 = __ldcs(pe),        f1 = __ldcs(pe + 1);
    float4 g0 = __ldcs(pe + 2048), g1 = __ldcs(pe + 2049);

    float excl[NCH];     // within-warp exclusive prefix of pair-sums
    float dfirst[NCH];   // delta of first element of the pair

    #pragma unroll
    for (int k = 0; k < NCH; k++) {
        float d0 = fmaf(Bcoef, softplus_fast(fmaf(f0.y, wa0, fmaf(f0.z, wa1, vba))), Acoef) * f0.y;
        float d1 = fmaf(Bcoef, softplus_fast(fmaf(f1.y, wa0, fmaf(f1.z, wa1, vba))), Acoef) * f1.y;

        // rotate pipeline; issue chunk k+2 loads (in flight across the warp scan)
        f0 = g0; f1 = g1;
        if (k + 2 < NCH) {
            const float4* pn = pe + (size_t)(k + 2) * 2048;
            g0 = __ldcs(pn); g1 = __ldcs(pn + 1);
        }

        // warp-local inclusive scan of pair sums (no barriers)
        float tsum = d0 + d1;
        float v = tsum;
        #pragma unroll
        for (int off = 1; off < 32; off <<= 1) {
            float u = __shfl_up_sync(0xffffffffu, v, off);
            if (lane >= off) v += u;
        }
        excl[k]   = v - tsum;
        dfirst[k] = d0;
        if (lane == 31) swtot[k][warp] = v;   // publish warp total (race-free: per-k slot)
    }
    __syncthreads();

    // ---- single cross-warp + cross-chunk pass (warp0 only) ----
    if (warp == 0) {
        float carry = s_init;                 // fold SOC_init into the running base
        #pragma unroll
        for (int k = 0; k < NCH; k++) {
            float wv = swtot[k][lane];
            #pragma unroll
            for (int off = 1; off < 32; off <<= 1) {
                float u = __shfl_up_sync(0xffffffffu, wv, off);
                if (lane >= off) wv += u;
            }
            __syncwarp();                     // all reads of swtot[k][*] done
            swtot[k][lane + 1] = carry + wv;  // slot w = carry + inclusive(w-1)
            if (lane == 0) swtot[k][0] = carry;
            carry += __shfl_sync(0xffffffffu, wv, 31);   // += chunk total
        }
    }
    __syncthreads();

    // ---- emit: out[s] = SOC_init + exclusive_prefix(s) ----
    #pragma unroll
    for (int k = 0; k < NCH; k++) {
        float x0v = swtot[k][warp] + excl[k];
        float2 o;
        o.x = x0v;
        o.y = x0v + dfirst[k];
        __stcs((float2*)outb + k * 1024 + tid, o);
    }
}

extern "C" void kernel_launch(void* const* d_in, const int* in_sizes, int n_in,
                              void* d_out, int out_size)
{
    (void)in_sizes; (void)n_in; (void)out_size;
    const float4* X  = (const float4*)d_in[0];
    const float*  SC = (const float*)d_in[1];
    const float*  W1 = (const float*)d_in[2];
    const float*  b1 = (const float*)d_in[3];
    const float*  W2 = (const float*)d_in[4];
    const float*  b2 = (const float*)d_in[5];
    const float*  Wa = (const float*)d_in[6];
    const float*  ba = (const float*)d_in[7];
    const float*  Wb = (const float*)d_in[8];
    const float*  bb = (const float*)d_in[9];
    float* out = (float*)d_out;

    soc_kernel<<<2048, NT>>>(X, SC, W1, b1, W2, b2, Wa, ba, Wb, bb, out);
}